// round 13
// baseline (speedup 1.0000x reference)
#include <cuda_runtime.h>
#include <cuda_bf16.h>

// DistortionLoss (eff_distloss) — two-kernel, one-quad-per-warp straight-line.
//
// R12 -> R13: unroll-4 hit 7.22 TB/s (90% spec); structure floor = main +
// 4.1us finalize node. Last lever is the main loop: make each warp process
// EXACTLY ONE quad of rows (B/4 = 65536 warps -> 8192 blocks) with no
// grid-stride loop at all: 12 independent LDG.128 issued straight after the
// bounds check, compute, reduce, retire. Fast-retiring blocks pipeline
// through the SM scheduler with no 2-iteration straggler tail.
// Reduction unchanged: block REDG atomicAdd -> O(1) self-resetting finalize.

#define LOSS_WEIGHT 0.01f
#define N_SAMPLES 128
#define BLOCK_THREADS 256
#define WARPS_PER_BLOCK (BLOCK_THREADS / 32)
#define ROWS_PER_WARP 4

__device__ double g_accum = 0.0;   // always 0 between launches

__device__ __forceinline__ float row_contrib(
    const float4 wv, const float4 mv, const float4 sv, const int lane)
{
    // uni term partial: sum s*w^2 over this lane's 4 elements
    float uni = sv.x * wv.x * wv.x;
    uni = fmaf(sv.y * wv.y, wv.y, uni);
    uni = fmaf(sv.z * wv.z, wv.z, uni);
    uni = fmaf(sv.w * wv.w, wv.w, uni);

    // wm = w * m
    const float wm0 = wv.x * mv.x;
    const float wm1 = wv.y * mv.y;
    const float wm2 = wv.z * mv.z;
    const float wm3 = wv.w * mv.w;

    // local exclusive prefixes within the 4-element chunk
    const float eW1 = wv.x;
    const float eW2 = eW1 + wv.y;
    const float eW3 = eW2 + wv.z;
    const float tW  = eW3 + wv.w;     // lane total of w

    const float eM1 = wm0;
    const float eM2 = eM1 + wm1;
    const float eM3 = eM2 + wm2;
    const float tM  = eM3 + wm3;      // lane total of wm

    // warp inclusive scan of lane totals (w and wm together; independent
    // chains pipeline their SHFL latencies)
    float iW = tW, iM = tM;
    #pragma unroll
    for (int off = 1; off < 32; off <<= 1) {
        const float aW = __shfl_up_sync(0xffffffffu, iW, off);
        const float aM = __shfl_up_sync(0xffffffffu, iM, off);
        if (lane >= off) { iW += aW; iM += aM; }
    }
    const float EW = iW - tW;   // exclusive warp prefix of w
    const float EM = iM - tM;   // exclusive warp prefix of wm

    // bi term: sum_k wm_k * exW_k - w_k * exWM_k  (exclusive prefixes)
    float bi;
    bi  = wm0 * EW          - wv.x * EM;
    bi += wm1 * (EW + eW1)  - wv.y * (EM + eM1);
    bi += wm2 * (EW + eW2)  - wv.z * (EM + eM2);
    bi += wm3 * (EW + eW3)  - wv.w * (EM + eM3);

    return (1.0f / 3.0f) * uni + 2.0f * bi;
}

__global__ __launch_bounds__(BLOCK_THREADS) void dl_main_kernel(
    const float* __restrict__ w,
    const float* __restrict__ m,
    const float* __restrict__ s,
    int B)
{
    const int lane   = threadIdx.x & 31;
    const int warpIn = threadIdx.x >> 5;
    const int gwarp  = (blockIdx.x * BLOCK_THREADS + threadIdx.x) >> 5;

    float acc = 0.0f;

    const int row = gwarp * ROWS_PER_WARP;
    if (row + ROWS_PER_WARP <= B) {
        const size_t b0 = (size_t)row * N_SAMPLES;
        const size_t b1 = b0 + N_SAMPLES;
        const size_t b2 = b1 + N_SAMPLES;
        const size_t b3 = b2 + N_SAMPLES;
        // 12 independent 16B loads issued before any compute
        const float4 wv0 = reinterpret_cast<const float4*>(w + b0)[lane];
        const float4 wv1 = reinterpret_cast<const float4*>(w + b1)[lane];
        const float4 wv2 = reinterpret_cast<const float4*>(w + b2)[lane];
        const float4 wv3 = reinterpret_cast<const float4*>(w + b3)[lane];
        const float4 mv0 = reinterpret_cast<const float4*>(m + b0)[lane];
        const float4 mv1 = reinterpret_cast<const float4*>(m + b1)[lane];
        const float4 mv2 = reinterpret_cast<const float4*>(m + b2)[lane];
        const float4 mv3 = reinterpret_cast<const float4*>(m + b3)[lane];
        const float4 sv0 = reinterpret_cast<const float4*>(s + b0)[lane];
        const float4 sv1 = reinterpret_cast<const float4*>(s + b1)[lane];
        const float4 sv2 = reinterpret_cast<const float4*>(s + b2)[lane];
        const float4 sv3 = reinterpret_cast<const float4*>(s + b3)[lane];

        acc += row_contrib(wv0, mv0, sv0, lane);
        acc += row_contrib(wv1, mv1, sv1, lane);
        acc += row_contrib(wv2, mv2, sv2, lane);
        acc += row_contrib(wv3, mv3, sv3, lane);
    } else {
        // tail warp: handle remaining rows one at a time
        for (int r = row; r < B; r++) {
            const size_t b0 = (size_t)r * N_SAMPLES;
            const float4 wv0 = reinterpret_cast<const float4*>(w + b0)[lane];
            const float4 mv0 = reinterpret_cast<const float4*>(m + b0)[lane];
            const float4 sv0 = reinterpret_cast<const float4*>(s + b0)[lane];
            acc += row_contrib(wv0, mv0, sv0, lane);
        }
    }

    // warp reduce
    #pragma unroll
    for (int off = 16; off > 0; off >>= 1)
        acc += __shfl_down_sync(0xffffffffu, acc, off);

    __shared__ float warp_sums[WARPS_PER_BLOCK];
    if (lane == 0) warp_sums[warpIn] = acc;
    __syncthreads();

    if (threadIdx.x == 0) {
        float blockAcc = 0.0f;
        #pragma unroll
        for (int i = 0; i < WARPS_PER_BLOCK; i++) blockAcc += warp_sums[i];
        atomicAdd(&g_accum, (double)blockAcc);   // REDG, single address
    }
}

__global__ void dl_finalize_kernel(float* __restrict__ out, float scale) {
    out[0] = (float)(g_accum * (double)scale);
    g_accum = 0.0;   // leave accumulator clean for the next replay
}

extern "C" void kernel_launch(void* const* d_in, const int* in_sizes, int n_in,
                              void* d_out, int out_size) {
    const float* w = (const float*)d_in[0];
    const float* m = (const float*)d_in[1];
    const float* s = (const float*)d_in[2];
    float* out = (float*)d_out;

    const int B = in_sizes[0] / N_SAMPLES;

    // One warp per ROWS_PER_WARP rows, straight-line (no grid-stride loop).
    const int rowsPerBlock = WARPS_PER_BLOCK * ROWS_PER_WARP;  // 32
    int blocks = (B + rowsPerBlock - 1) / rowsPerBlock;        // 8192 @ B=262144
    if (blocks < 1) blocks = 1;

    dl_main_kernel<<<blocks, BLOCK_THREADS>>>(w, m, s, B);
    dl_finalize_kernel<<<1, 1>>>(out, LOSS_WEIGHT / (float)B);
}